// round 2
// baseline (speedup 1.0000x reference)
#include <cuda_runtime.h>
#include <math.h>

// Problem constants
#define BB   2
#define SS   2048
#define DIMM 4096
#define NHH  32
#define NKVV 8
#define HDD  128
#define MROWS (BB*SS)            // 4096
#define OUT_ELEMS   (MROWS*DIMM) // 16777216
#define KV_ELEMS    (MROWS*NKVV*HDD) // 4194304

// Scratch (device globals -- no allocation allowed)
__device__ float g_q[(size_t)MROWS * DIMM];    // roped Q, (b,s,h,d)
__device__ float g_ctx[(size_t)MROWS * DIMM];  // attention output ctx, (b,s,h,d)

// ----------------------------------------------------------------------------
// SGEMM: C[M,N] = A[M,K] * B[K,N], all row-major, fp32.
// 128x128 block tile, BK=8, 256 threads, 8x8 per-thread micro tile.
// Requires M%128==0, N%128==0, K%8==0 (true for all our shapes).
// ----------------------------------------------------------------------------
__global__ __launch_bounds__(256) void sgemm_kernel(
    const float* __restrict__ A, const float* __restrict__ Bm,
    float* __restrict__ C, int M, int N, int K)
{
    __shared__ float As[8][128];
    __shared__ float Bs[8][128];

    const int tid = threadIdx.x;
    const int bm = blockIdx.y * 128;
    const int bn = blockIdx.x * 128;

    const int ar = tid >> 1;          // 0..127
    const int ac = (tid & 1) * 4;     // 0 or 4
    const int br = tid >> 5;          // 0..7
    const int bc = (tid & 31) * 4;    // 0..124
    const int ty8 = (tid >> 4) * 8;   // row base in tile
    const int tx8 = (tid & 15) * 8;   // col base in tile

    float acc[8][8];
#pragma unroll
    for (int i = 0; i < 8; i++)
#pragma unroll
        for (int j = 0; j < 8; j++) acc[i][j] = 0.0f;

    for (int k0 = 0; k0 < K; k0 += 8) {
        float4 av = *(const float4*)(A + (size_t)(bm + ar) * K + k0 + ac);
        float4 bv = *(const float4*)(Bm + (size_t)(k0 + br) * N + bn + bc);
        As[ac + 0][ar] = av.x;
        As[ac + 1][ar] = av.y;
        As[ac + 2][ar] = av.z;
        As[ac + 3][ar] = av.w;
        *(float4*)(&Bs[br][bc]) = bv;
        __syncthreads();

#pragma unroll
        for (int kk = 0; kk < 8; kk++) {
            float4 a0 = *(const float4*)(&As[kk][ty8]);
            float4 a1 = *(const float4*)(&As[kk][ty8 + 4]);
            float4 b0 = *(const float4*)(&Bs[kk][tx8]);
            float4 b1 = *(const float4*)(&Bs[kk][tx8 + 4]);
            float ra[8] = {a0.x, a0.y, a0.z, a0.w, a1.x, a1.y, a1.z, a1.w};
            float rb[8] = {b0.x, b0.y, b0.z, b0.w, b1.x, b1.y, b1.z, b1.w};
#pragma unroll
            for (int i = 0; i < 8; i++)
#pragma unroll
                for (int j = 0; j < 8; j++)
                    acc[i][j] = fmaf(ra[i], rb[j], acc[i][j]);
        }
        __syncthreads();
    }

#pragma unroll
    for (int i = 0; i < 8; i++) {
        float4* c0 = (float4*)(C + (size_t)(bm + ty8 + i) * N + bn + tx8);
        c0[0] = make_float4(acc[i][0], acc[i][1], acc[i][2], acc[i][3]);
        c0[1] = make_float4(acc[i][4], acc[i][5], acc[i][6], acc[i][7]);
    }
}

// ----------------------------------------------------------------------------
// RoPE, in place. data layout: [rows][heads*128], pairs are (2i, 2i+1).
// fc layout: [SS][64][2] (cos, sin).  rows = BB*SS, s = row % SS.
// ----------------------------------------------------------------------------
__global__ void rope_kernel(float* __restrict__ data,
                            const float* __restrict__ fc,
                            int rows, int heads)
{
    int idx = blockIdx.x * blockDim.x + threadIdx.x;
    int total = rows * heads * 64;
    if (idx >= total) return;
    int i = idx & 63;
    int h = (idx >> 6) % heads;
    int row = idx / (heads * 64);
    int s = row & (SS - 1);
    float c = fc[(size_t)s * 128 + i * 2 + 0];
    float sn = fc[(size_t)s * 128 + i * 2 + 1];
    float* p = data + (size_t)row * heads * HDD + h * HDD + i * 2;
    float xr = p[0], xi = p[1];
    p[0] = xr * c - xi * sn;
    p[1] = xr * sn + xi * c;
}

// ----------------------------------------------------------------------------
// Flash-style GQA attention, fp32.
// Block: 64 queries of one (b, h). Loop over 2048 keys in tiles of 64.
// Q: g_q layout (b,s,NH,HD). K/V layout (b,s,NKV,HD). Out: g_ctx (b,s,NH,HD).
// 256 threads: S tile 4x4/thread (16x16 grid), O tile 4 rows x 8 cols/thread.
// ----------------------------------------------------------------------------
#define ATTN_SMEM_FLOATS (128*65 + 128*65 + 64*128 + 64*65)
__global__ __launch_bounds__(256) void attn_kernel(
    const float* __restrict__ Q, const float* __restrict__ K,
    const float* __restrict__ V, float* __restrict__ O)
{
    extern __shared__ float sm[];
    float* Qs = sm;                // [128][65]  Qs[d*65 + r]
    float* Ks = Qs + 128 * 65;     // [128][65]  Ks[d*65 + c]
    float* Vs = Ks + 128 * 65;     // [64][128]  Vs[k*128 + c]
    float* Pt = Vs + 64 * 128;     // [64][65]   Pt[c*65 + r]

    const int tid = threadIdx.x;
    const int ty = tid >> 4;     // 0..15 (row group)
    const int tx = tid & 15;     // 0..15 (col group)
    const int qtile = blockIdx.x;
    const int h = blockIdx.y;
    const int b = blockIdx.z;
    const int g = h >> 2;        // N_REP = 4

    const float* qbase = Q + ((size_t)b * SS + qtile * 64) * DIMM + h * HDD;
    const float* kbase = K + (size_t)b * SS * (NKVV * HDD) + g * HDD;
    const float* vbase = V + (size_t)b * SS * (NKVV * HDD) + g * HDD;

    // Load Q tile (transposed into smem)
    for (int idx = tid; idx < 64 * 128; idx += 256) {
        int r = idx >> 7, d = idx & 127;
        Qs[d * 65 + r] = qbase[(size_t)r * DIMM + d];
    }

    const float scale = 0.08838834764831845f; // 1/sqrt(128)
    float m[4], l[4], acc[4][8];
#pragma unroll
    for (int i = 0; i < 4; i++) {
        m[i] = -1e30f;
        l[i] = 0.0f;
#pragma unroll
        for (int j = 0; j < 8; j++) acc[i][j] = 0.0f;
    }

    for (int kt = 0; kt < SS / 64; kt++) {
        __syncthreads();  // protect Ks/Vs/Pt from previous iteration readers
        // load K,V tiles
        for (int idx = tid; idx < 64 * 128; idx += 256) {
            int r = idx >> 7, d = idx & 127;
            Ks[d * 65 + r] = kbase[(size_t)(kt * 64 + r) * (NKVV * HDD) + d];
            Vs[r * 128 + d] = vbase[(size_t)(kt * 64 + r) * (NKVV * HDD) + d];
        }
        __syncthreads();

        // Phase A: S = Q K^T (this thread: rows ty*4+i, cols tx*4+j)
        float s[4][4];
#pragma unroll
        for (int i = 0; i < 4; i++)
#pragma unroll
            for (int j = 0; j < 4; j++) s[i][j] = 0.0f;

        for (int kk = 0; kk < 128; kk++) {
            float ra[4], rb[4];
#pragma unroll
            for (int i = 0; i < 4; i++) ra[i] = Qs[kk * 65 + ty * 4 + i];
#pragma unroll
            for (int j = 0; j < 4; j++) rb[j] = Ks[kk * 65 + tx * 4 + j];
#pragma unroll
            for (int i = 0; i < 4; i++)
#pragma unroll
                for (int j = 0; j < 4; j++)
                    s[i][j] = fmaf(ra[i], rb[j], s[i][j]);
        }

        // Phase B: online softmax update (row spread over 16 lanes, same warp half)
#pragma unroll
        for (int i = 0; i < 4; i++) {
            float mx = s[i][0];
#pragma unroll
            for (int j = 1; j < 4; j++) mx = fmaxf(mx, s[i][j]);
            mx *= scale;
#pragma unroll
            for (int off = 8; off > 0; off >>= 1)
                mx = fmaxf(mx, __shfl_xor_sync(0xffffffffu, mx, off));
            float mnew = fmaxf(m[i], mx);
            float corr = __expf(m[i] - mnew);
            float ls = 0.0f;
#pragma unroll
            for (int j = 0; j < 4; j++) {
                float p = __expf(s[i][j] * scale - mnew);
                Pt[(tx * 4 + j) * 65 + ty * 4 + i] = p;
                ls += p;
            }
#pragma unroll
            for (int off = 8; off > 0; off >>= 1)
                ls += __shfl_xor_sync(0xffffffffu, ls, off);
            l[i] = l[i] * corr + ls;
            m[i] = mnew;
#pragma unroll
            for (int jj = 0; jj < 8; jj++) acc[i][jj] *= corr;
        }
        __syncthreads();

        // Phase C: O += P V (this thread: rows ty*4+i, cols tx + 16*jj)
        for (int k = 0; k < 64; k++) {
            float pa[4];
#pragma unroll
            for (int i = 0; i < 4; i++) pa[i] = Pt[k * 65 + ty * 4 + i];
            float vb[8];
#pragma unroll
            for (int jj = 0; jj < 8; jj++) vb[jj] = Vs[k * 128 + tx + 16 * jj];
#pragma unroll
            for (int i = 0; i < 4; i++)
#pragma unroll
                for (int jj = 0; jj < 8; jj++)
                    acc[i][jj] = fmaf(pa[i], vb[jj], acc[i][jj]);
        }
    }

    // Write ctx (b,s,h,d)
    float* obase = O + ((size_t)b * SS + qtile * 64) * DIMM + h * HDD;
#pragma unroll
    for (int i = 0; i < 4; i++) {
        float inv = 1.0f / l[i];
#pragma unroll
        for (int jj = 0; jj < 8; jj++)
            obase[(size_t)(ty * 4 + i) * DIMM + tx + 16 * jj] = acc[i][jj] * inv;
    }
}

// ----------------------------------------------------------------------------
// Launch
// ----------------------------------------------------------------------------
extern "C" void kernel_launch(void* const* d_in, const int* in_sizes, int n_in,
                              void* d_out, int out_size)
{
    const float* x  = (const float*)d_in[0];
    const float* fc = (const float*)d_in[1];
    const float* wq = (const float*)d_in[2];
    const float* wk = (const float*)d_in[3];
    const float* wv = (const float*)d_in[4];
    const float* wo = (const float*)d_in[5];

    float* out  = (float*)d_out;                 // (b,s,DIM)
    float* kout = out + (size_t)OUT_ELEMS;       // new_k (b,s,NKV,HD)
    float* vout = kout + (size_t)KV_ELEMS;       // new_v (b,s,NKV,HD)

    float* qptr = nullptr;
    float* ctxptr = nullptr;
    cudaGetSymbolAddress((void**)&qptr, g_q);
    cudaGetSymbolAddress((void**)&ctxptr, g_ctx);

    // Q/K/V projections. K and V write directly into the output buffer.
    {
        dim3 gq(DIMM / 128, MROWS / 128);
        sgemm_kernel<<<gq, 256>>>(x, wq, qptr, MROWS, DIMM, DIMM);
        dim3 gkv((NKVV * HDD) / 128, MROWS / 128);
        sgemm_kernel<<<gkv, 256>>>(x, wk, kout, MROWS, NKVV * HDD, DIMM);
        sgemm_kernel<<<gkv, 256>>>(x, wv, vout, MROWS, NKVV * HDD, DIMM);
    }

    // RoPE (in place): Q in scratch, K in the output buffer (becomes new_k).
    {
        int totq = MROWS * NHH * 64;
        rope_kernel<<<(totq + 255) / 256, 256>>>(qptr, fc, MROWS, NHH);
        int totk = MROWS * NKVV * 64;
        rope_kernel<<<(totk + 255) / 256, 256>>>(kout, fc, MROWS, NKVV);
    }

    // Attention
    {
        size_t smem = ATTN_SMEM_FLOATS * sizeof(float);
        cudaFuncSetAttribute(attn_kernel,
                             cudaFuncAttributeMaxDynamicSharedMemorySize,
                             (int)smem);
        dim3 grid(SS / 64, NHH, BB);
        attn_kernel<<<grid, 256, smem>>>(qptr, kout, vout, ctxptr);
    }

    // Output projection
    {
        dim3 go(DIMM / 128, MROWS / 128);
        sgemm_kernel<<<go, 256>>>(ctxptr, wo, out, MROWS, DIMM, DIMM);
    }
}

// round 3
// speedup vs baseline: 1.6218x; 1.6218x over previous
#include <cuda_runtime.h>
#include <math.h>
#include <stdint.h>

// Problem constants
#define BB   2
#define SS   2048
#define DIMM 4096
#define NHH  32
#define NKVV 8
#define HDD  128
#define MROWS (BB*SS)            // 4096
#define OUT_ELEMS   (MROWS*DIMM) // 16777216
#define KV_ELEMS    (MROWS*NKVV*HDD) // 4194304

// Scratch (device globals -- no allocation allowed)
__device__ float g_q[(size_t)MROWS * DIMM];    // roped Q, (b,s,h,d)
__device__ float g_ctx[(size_t)MROWS * DIMM];  // attention output ctx, (b,s,h,d)

__device__ __forceinline__ uint32_t f2tf32(float f) {
    uint32_t u;
    asm volatile("cvt.rna.tf32.f32 %0, %1;" : "=r"(u) : "f"(f));
    return u;
}

// ----------------------------------------------------------------------------
// TF32 tensor-core GEMM: C[M,N] = A[M,K] * B[K,N], row-major fp32 in/out.
// 128x128 block tile, BK=32, 256 threads = 8 warps (2M x 4N), warp tile 64x32.
// mma.sync.aligned.m16n8k8.row.col.f32.tf32.tf32.f32
// Requires M%128==0, N%128==0, K%32==0.
// ----------------------------------------------------------------------------
#define BK 32
#define LDS_PAD 132   // 128 + 4 pad, conflict-free fragment loads

__global__ __launch_bounds__(256) void gemm_tf32_kernel(
    const float* __restrict__ A, const float* __restrict__ Bm,
    float* __restrict__ C, int M, int N, int K)
{
    __shared__ uint32_t As[BK][LDS_PAD];  // k-major: As[k][m]
    __shared__ uint32_t Bs[BK][LDS_PAD];  // k-major: Bs[k][n]

    const int tid   = threadIdx.x;
    const int lane  = tid & 31;
    const int warp  = tid >> 5;
    const int warpM = warp >> 2;          // 0..1
    const int warpN = warp & 3;           // 0..3
    const int bm = blockIdx.y * 128;
    const int bn = blockIdx.x * 128;

    const int qk = lane & 3;              // lane%4 -> k within frag
    const int qr = lane >> 2;             // lane/4 -> row/col within frag

    float acc[4][4][4];
#pragma unroll
    for (int i = 0; i < 4; i++)
#pragma unroll
        for (int j = 0; j < 4; j++)
#pragma unroll
            for (int r = 0; r < 4; r++) acc[i][j][r] = 0.0f;

    for (int k0 = 0; k0 < K; k0 += BK) {
        // --- load A tile: 128 rows x 32 k, coalesced float4 along K ---
#pragma unroll
        for (int l = 0; l < 4; l++) {
            int flat = l * 256 + tid;
            int m  = flat >> 3;           // 0..127
            int kg = flat & 7;            // 0..7 (float4 group)
            float4 v = *(const float4*)(A + (size_t)(bm + m) * K + k0 + kg * 4);
            As[kg * 4 + 0][m] = f2tf32(v.x);
            As[kg * 4 + 1][m] = f2tf32(v.y);
            As[kg * 4 + 2][m] = f2tf32(v.z);
            As[kg * 4 + 3][m] = f2tf32(v.w);
        }
        // --- load B tile: 32 k x 128 n, coalesced float4 along N ---
#pragma unroll
        for (int l = 0; l < 4; l++) {
            int flat = l * 256 + tid;
            int k  = flat >> 5;           // 0..31
            int ng = flat & 31;           // 0..31 (float4 group)
            float4 v = *(const float4*)(Bm + (size_t)(k0 + k) * N + bn + ng * 4);
            Bs[k][ng * 4 + 0] = f2tf32(v.x);
            Bs[k][ng * 4 + 1] = f2tf32(v.y);
            Bs[k][ng * 4 + 2] = f2tf32(v.z);
            Bs[k][ng * 4 + 3] = f2tf32(v.w);
        }
        __syncthreads();

#pragma unroll
        for (int kk = 0; kk < BK; kk += 8) {
            uint32_t af[4][4], bf[4][2];
#pragma unroll
            for (int mf = 0; mf < 4; mf++) {
                int row = warpM * 64 + mf * 16 + qr;
                af[mf][0] = As[kk + qk][row];
                af[mf][1] = As[kk + qk][row + 8];
                af[mf][2] = As[kk + qk + 4][row];
                af[mf][3] = As[kk + qk + 4][row + 8];
            }
#pragma unroll
            for (int nf = 0; nf < 4; nf++) {
                int col = warpN * 32 + nf * 8 + qr;
                bf[nf][0] = Bs[kk + qk][col];
                bf[nf][1] = Bs[kk + qk + 4][col];
            }
#pragma unroll
            for (int mf = 0; mf < 4; mf++)
#pragma unroll
                for (int nf = 0; nf < 4; nf++) {
                    asm volatile(
                        "mma.sync.aligned.m16n8k8.row.col.f32.tf32.tf32.f32 "
                        "{%0,%1,%2,%3}, {%4,%5,%6,%7}, {%8,%9}, {%0,%1,%2,%3};"
                        : "+f"(acc[mf][nf][0]), "+f"(acc[mf][nf][1]),
                          "+f"(acc[mf][nf][2]), "+f"(acc[mf][nf][3])
                        : "r"(af[mf][0]), "r"(af[mf][1]),
                          "r"(af[mf][2]), "r"(af[mf][3]),
                          "r"(bf[nf][0]), "r"(bf[nf][1]));
                }
        }
        __syncthreads();
    }

    // --- epilogue: c0,c1 -> (row, 2q), (row, 2q+1); c2,c3 -> row+8 ---
#pragma unroll
    for (int mf = 0; mf < 4; mf++) {
        int row = bm + warpM * 64 + mf * 16 + qr;
#pragma unroll
        for (int nf = 0; nf < 4; nf++) {
            int col = bn + warpN * 32 + nf * 8 + 2 * qk;
            float2* p0 = (float2*)(C + (size_t)row * N + col);
            float2* p1 = (float2*)(C + (size_t)(row + 8) * N + col);
            *p0 = make_float2(acc[mf][nf][0], acc[mf][nf][1]);
            *p1 = make_float2(acc[mf][nf][2], acc[mf][nf][3]);
        }
    }
}

// ----------------------------------------------------------------------------
// RoPE, in place. data layout: [rows][heads*128], pairs are (2i, 2i+1).
// ----------------------------------------------------------------------------
__global__ void rope_kernel(float* __restrict__ data,
                            const float* __restrict__ fc,
                            int rows, int heads)
{
    int idx = blockIdx.x * blockDim.x + threadIdx.x;
    int total = rows * heads * 64;
    if (idx >= total) return;
    int i = idx & 63;
    int h = (idx >> 6) % heads;
    int row = idx / (heads * 64);
    int s = row & (SS - 1);
    float c = fc[(size_t)s * 128 + i * 2 + 0];
    float sn = fc[(size_t)s * 128 + i * 2 + 1];
    float* p = data + (size_t)row * heads * HDD + h * HDD + i * 2;
    float xr = p[0], xi = p[1];
    p[0] = xr * c - xi * sn;
    p[1] = xr * sn + xi * c;
}

// ----------------------------------------------------------------------------
// Flash-style GQA attention, fp32 (unchanged from R1 baseline).
// ----------------------------------------------------------------------------
#define ATTN_SMEM_FLOATS (128*65 + 128*65 + 64*128 + 64*65)
__global__ __launch_bounds__(256) void attn_kernel(
    const float* __restrict__ Q, const float* __restrict__ K,
    const float* __restrict__ V, float* __restrict__ O)
{
    extern __shared__ float sm[];
    float* Qs = sm;                // [128][65]  Qs[d*65 + r]
    float* Ks = Qs + 128 * 65;     // [128][65]  Ks[d*65 + c]
    float* Vs = Ks + 128 * 65;     // [64][128]  Vs[k*128 + c]
    float* Pt = Vs + 64 * 128;     // [64][65]   Pt[c*65 + r]

    const int tid = threadIdx.x;
    const int ty = tid >> 4;
    const int tx = tid & 15;
    const int qtile = blockIdx.x;
    const int h = blockIdx.y;
    const int b = blockIdx.z;
    const int g = h >> 2;        // N_REP = 4

    const float* qbase = Q + ((size_t)b * SS + qtile * 64) * DIMM + h * HDD;
    const float* kbase = K + (size_t)b * SS * (NKVV * HDD) + g * HDD;
    const float* vbase = V + (size_t)b * SS * (NKVV * HDD) + g * HDD;

    for (int idx = tid; idx < 64 * 128; idx += 256) {
        int r = idx >> 7, d = idx & 127;
        Qs[d * 65 + r] = qbase[(size_t)r * DIMM + d];
    }

    const float scale = 0.08838834764831845f;
    float m[4], l[4], acc[4][8];
#pragma unroll
    for (int i = 0; i < 4; i++) {
        m[i] = -1e30f;
        l[i] = 0.0f;
#pragma unroll
        for (int j = 0; j < 8; j++) acc[i][j] = 0.0f;
    }

    for (int kt = 0; kt < SS / 64; kt++) {
        __syncthreads();
        for (int idx = tid; idx < 64 * 128; idx += 256) {
            int r = idx >> 7, d = idx & 127;
            Ks[d * 65 + r] = kbase[(size_t)(kt * 64 + r) * (NKVV * HDD) + d];
            Vs[r * 128 + d] = vbase[(size_t)(kt * 64 + r) * (NKVV * HDD) + d];
        }
        __syncthreads();

        float s[4][4];
#pragma unroll
        for (int i = 0; i < 4; i++)
#pragma unroll
            for (int j = 0; j < 4; j++) s[i][j] = 0.0f;

        for (int kk = 0; kk < 128; kk++) {
            float ra[4], rb[4];
#pragma unroll
            for (int i = 0; i < 4; i++) ra[i] = Qs[kk * 65 + ty * 4 + i];
#pragma unroll
            for (int j = 0; j < 4; j++) rb[j] = Ks[kk * 65 + tx * 4 + j];
#pragma unroll
            for (int i = 0; i < 4; i++)
#pragma unroll
                for (int j = 0; j < 4; j++)
                    s[i][j] = fmaf(ra[i], rb[j], s[i][j]);
        }

#pragma unroll
        for (int i = 0; i < 4; i++) {
            float mx = s[i][0];
#pragma unroll
            for (int j = 1; j < 4; j++) mx = fmaxf(mx, s[i][j]);
            mx *= scale;
#pragma unroll
            for (int off = 8; off > 0; off >>= 1)
                mx = fmaxf(mx, __shfl_xor_sync(0xffffffffu, mx, off));
            float mnew = fmaxf(m[i], mx);
            float corr = __expf(m[i] - mnew);
            float ls = 0.0f;
#pragma unroll
            for (int j = 0; j < 4; j++) {
                float p = __expf(s[i][j] * scale - mnew);
                Pt[(tx * 4 + j) * 65 + ty * 4 + i] = p;
                ls += p;
            }
#pragma unroll
            for (int off = 8; off > 0; off >>= 1)
                ls += __shfl_xor_sync(0xffffffffu, ls, off);
            l[i] = l[i] * corr + ls;
            m[i] = mnew;
#pragma unroll
            for (int jj = 0; jj < 8; jj++) acc[i][jj] *= corr;
        }
        __syncthreads();

        for (int k = 0; k < 64; k++) {
            float pa[4];
#pragma unroll
            for (int i = 0; i < 4; i++) pa[i] = Pt[k * 65 + ty * 4 + i];
            float vb[8];
#pragma unroll
            for (int jj = 0; jj < 8; jj++) vb[jj] = Vs[k * 128 + tx + 16 * jj];
#pragma unroll
            for (int i = 0; i < 4; i++)
#pragma unroll
                for (int jj = 0; jj < 8; jj++)
                    acc[i][jj] = fmaf(pa[i], vb[jj], acc[i][jj]);
        }
    }

    float* obase = O + ((size_t)b * SS + qtile * 64) * DIMM + h * HDD;
#pragma unroll
    for (int i = 0; i < 4; i++) {
        float inv = 1.0f / l[i];
#pragma unroll
        for (int jj = 0; jj < 8; jj++)
            obase[(size_t)(ty * 4 + i) * DIMM + tx + 16 * jj] = acc[i][jj] * inv;
    }
}

// ----------------------------------------------------------------------------
// Launch
// ----------------------------------------------------------------------------
extern "C" void kernel_launch(void* const* d_in, const int* in_sizes, int n_in,
                              void* d_out, int out_size)
{
    const float* x  = (const float*)d_in[0];
    const float* fc = (const float*)d_in[1];
    const float* wq = (const float*)d_in[2];
    const float* wk = (const float*)d_in[3];
    const float* wv = (const float*)d_in[4];
    const float* wo = (const float*)d_in[5];

    float* out  = (float*)d_out;                 // (b,s,DIM)
    float* kout = out + (size_t)OUT_ELEMS;       // new_k (b,s,NKV,HD)
    float* vout = kout + (size_t)KV_ELEMS;       // new_v (b,s,NKV,HD)

    float* qptr = nullptr;
    float* ctxptr = nullptr;
    cudaGetSymbolAddress((void**)&qptr, g_q);
    cudaGetSymbolAddress((void**)&ctxptr, g_ctx);

    // Q/K/V projections (tensor cores, tf32). K/V write straight to output buf.
    {
        dim3 gq(DIMM / 128, MROWS / 128);
        gemm_tf32_kernel<<<gq, 256>>>(x, wq, qptr, MROWS, DIMM, DIMM);
        dim3 gkv((NKVV * HDD) / 128, MROWS / 128);
        gemm_tf32_kernel<<<gkv, 256>>>(x, wk, kout, MROWS, NKVV * HDD, DIMM);
        gemm_tf32_kernel<<<gkv, 256>>>(x, wv, vout, MROWS, NKVV * HDD, DIMM);
    }

    // RoPE (in place)
    {
        int totq = MROWS * NHH * 64;
        rope_kernel<<<(totq + 255) / 256, 256>>>(qptr, fc, MROWS, NHH);
        int totk = MROWS * NKVV * 64;
        rope_kernel<<<(totk + 255) / 256, 256>>>(kout, fc, MROWS, NKVV);
    }

    // Attention
    {
        size_t smem = ATTN_SMEM_FLOATS * sizeof(float);
        cudaFuncSetAttribute(attn_kernel,
                             cudaFuncAttributeMaxDynamicSharedMemorySize,
                             (int)smem);
        dim3 grid(SS / 64, NHH, BB);
        attn_kernel<<<grid, 256, smem>>>(qptr, kout, vout, ctxptr);
    }

    // Output projection (tensor cores, tf32)
    {
        dim3 go(DIMM / 128, MROWS / 128);
        gemm_tf32_kernel<<<go, 256>>>(ctxptr, wo, out, MROWS, DIMM, DIMM);
    }
}

// round 4
// speedup vs baseline: 1.8573x; 1.1452x over previous
#include <cuda_runtime.h>
#include <math.h>
#include <stdint.h>

// Problem constants
#define BB   2
#define SS   2048
#define DIMM 4096
#define NHH  32
#define NKVV 8
#define HDD  128
#define MROWS (BB*SS)            // 4096
#define OUT_ELEMS   (MROWS*DIMM) // 16777216
#define KV_ELEMS    (MROWS*NKVV*HDD) // 4194304

// Scratch (device globals -- no allocation allowed)
__device__ float g_q[(size_t)MROWS * DIMM];    // roped Q, (b,s,h,d)
__device__ float g_ctx[(size_t)MROWS * DIMM];  // attention output ctx, (b,s,h,d)

__device__ __forceinline__ uint32_t f2tf32(float f) {
    uint32_t u;
    asm volatile("cvt.rna.tf32.f32 %0, %1;" : "=r"(u) : "f"(f));
    return u;
}

__device__ __forceinline__ void cp_async16(uint32_t dst, const void* src) {
    asm volatile("cp.async.ca.shared.global [%0], [%1], 16;\n" :: "r"(dst), "l"(src));
}
__device__ __forceinline__ void cp_commit() {
    asm volatile("cp.async.commit_group;\n");
}
template <int W>
__device__ __forceinline__ void cp_wait() {
    asm volatile("cp.async.wait_group %0;\n" :: "n"(W));
}

// ----------------------------------------------------------------------------
// TF32 tensor-core GEMM, 2-stage cp.async double buffered.
// C[M,N] = A[M,K] * B[K,N], row-major fp32 in/out.
// 128x128 block tile, BK=32, 256 threads = 8 warps (2M x 4N), warp tile 64x32.
// A smem: [128][36] row-major (stride 36 -> conflict-free frag reads)
// B smem: [32][136] row-major (stride 136 -> conflict-free frag reads)
// ----------------------------------------------------------------------------
#define BK 32
#define A_STRIDE 36
#define B_STRIDE 136
#define A_STAGE (128 * A_STRIDE)       // floats per A stage
#define B_STAGE (BK * B_STRIDE)        // floats per B stage
#define GEMM_SMEM_FLOATS (2 * A_STAGE + 2 * B_STAGE)

__global__ __launch_bounds__(256) void gemm_tf32_kernel(
    const float* __restrict__ A, const float* __restrict__ Bm,
    float* __restrict__ C, int M, int N, int K)
{
    extern __shared__ float sm[];
    float* AsB = sm;                     // [2][128][A_STRIDE]
    float* BsB = sm + 2 * A_STAGE;       // [2][BK][B_STRIDE]

    const int tid   = threadIdx.x;
    const int lane  = tid & 31;
    const int warp  = tid >> 5;
    const int warpM = warp >> 2;          // 0..1
    const int warpN = warp & 3;           // 0..3
    const int bm = blockIdx.y * 128;
    const int bn = blockIdx.x * 128;

    const int qk = lane & 3;              // lane%4
    const int qr = lane >> 2;             // lane/4

    // copy indices (fixed per thread)
    const int cam = tid >> 1;             // unused placeholder
    (void)cam;

    const int ntiles = K / BK;

    float acc[4][4][4];
#pragma unroll
    for (int i = 0; i < 4; i++)
#pragma unroll
        for (int j = 0; j < 4; j++)
#pragma unroll
            for (int r = 0; r < 4; r++) acc[i][j][r] = 0.0f;

    // ---- tile loader: issue cp.async for tile t into stage st ----
    auto load_tile = [&](int t, int st) {
        const float* Asrc = A + (size_t)bm * K + t * BK;
        float* Ad = AsB + st * A_STAGE;
#pragma unroll
        for (int l = 0; l < 4; l++) {
            int flat = l * 256 + tid;
            int m  = flat >> 3;           // 0..127
            int kg = flat & 7;            // 0..7
            uint32_t dst = (uint32_t)__cvta_generic_to_shared(Ad + m * A_STRIDE + kg * 4);
            cp_async16(dst, Asrc + (size_t)m * K + kg * 4);
        }
        const float* Bsrc = Bm + (size_t)(t * BK) * N + bn;
        float* Bd = BsB + st * B_STAGE;
#pragma unroll
        for (int l = 0; l < 4; l++) {
            int flat = l * 256 + tid;
            int k  = flat >> 5;           // 0..31
            int ng = flat & 31;           // 0..31
            uint32_t dst = (uint32_t)__cvta_generic_to_shared(Bd + k * B_STRIDE + ng * 4);
            cp_async16(dst, Bsrc + (size_t)k * N + ng * 4);
        }
        cp_commit();
    };

    load_tile(0, 0);

    for (int t = 0; t < ntiles; t++) {
        const int st = t & 1;
        if (t + 1 < ntiles) {
            load_tile(t + 1, st ^ 1);
            cp_wait<1>();
        } else {
            cp_wait<0>();
        }
        __syncthreads();

        const float* As = AsB + st * A_STAGE;
        const float* Bs = BsB + st * B_STAGE;

#pragma unroll
        for (int kk = 0; kk < BK; kk += 8) {
            uint32_t af[4][4], bf[4][2];
#pragma unroll
            for (int mf = 0; mf < 4; mf++) {
                int row = warpM * 64 + mf * 16 + qr;
                af[mf][0] = f2tf32(As[row * A_STRIDE + kk + qk]);
                af[mf][1] = f2tf32(As[(row + 8) * A_STRIDE + kk + qk]);
                af[mf][2] = f2tf32(As[row * A_STRIDE + kk + qk + 4]);
                af[mf][3] = f2tf32(As[(row + 8) * A_STRIDE + kk + qk + 4]);
            }
#pragma unroll
            for (int nf = 0; nf < 4; nf++) {
                int col = warpN * 32 + nf * 8 + qr;
                bf[nf][0] = f2tf32(Bs[(kk + qk) * B_STRIDE + col]);
                bf[nf][1] = f2tf32(Bs[(kk + qk + 4) * B_STRIDE + col]);
            }
#pragma unroll
            for (int mf = 0; mf < 4; mf++)
#pragma unroll
                for (int nf = 0; nf < 4; nf++) {
                    asm volatile(
                        "mma.sync.aligned.m16n8k8.row.col.f32.tf32.tf32.f32 "
                        "{%0,%1,%2,%3}, {%4,%5,%6,%7}, {%8,%9}, {%0,%1,%2,%3};"
                        : "+f"(acc[mf][nf][0]), "+f"(acc[mf][nf][1]),
                          "+f"(acc[mf][nf][2]), "+f"(acc[mf][nf][3])
                        : "r"(af[mf][0]), "r"(af[mf][1]),
                          "r"(af[mf][2]), "r"(af[mf][3]),
                          "r"(bf[nf][0]), "r"(bf[nf][1]));
                }
        }
        __syncthreads();
    }

    // epilogue
#pragma unroll
    for (int mf = 0; mf < 4; mf++) {
        int row = bm + warpM * 64 + mf * 16 + qr;
#pragma unroll
        for (int nf = 0; nf < 4; nf++) {
            int col = bn + warpN * 32 + nf * 8 + 2 * qk;
            float2* p0 = (float2*)(C + (size_t)row * N + col);
            float2* p1 = (float2*)(C + (size_t)(row + 8) * N + col);
            *p0 = make_float2(acc[mf][nf][0], acc[mf][nf][1]);
            *p1 = make_float2(acc[mf][nf][2], acc[mf][nf][3]);
        }
    }
}

// ----------------------------------------------------------------------------
// RoPE, in place. data layout: [rows][heads*128], pairs are (2i, 2i+1).
// ----------------------------------------------------------------------------
__global__ void rope_kernel(float* __restrict__ data,
                            const float* __restrict__ fc,
                            int rows, int heads)
{
    int idx = blockIdx.x * blockDim.x + threadIdx.x;
    int total = rows * heads * 64;
    if (idx >= total) return;
    int i = idx & 63;
    int h = (idx >> 6) % heads;
    int row = idx / (heads * 64);
    int s = row & (SS - 1);
    float c = fc[(size_t)s * 128 + i * 2 + 0];
    float sn = fc[(size_t)s * 128 + i * 2 + 1];
    float* p = data + (size_t)row * heads * HDD + h * HDD + i * 2;
    float xr = p[0], xi = p[1];
    p[0] = xr * c - xi * sn;
    p[1] = xr * sn + xi * c;
}

// ----------------------------------------------------------------------------
// Flash-style GQA attention, fp32 (unchanged).
// ----------------------------------------------------------------------------
#define ATTN_SMEM_FLOATS (128*65 + 128*65 + 64*128 + 64*65)
__global__ __launch_bounds__(256) void attn_kernel(
    const float* __restrict__ Q, const float* __restrict__ K,
    const float* __restrict__ V, float* __restrict__ O)
{
    extern __shared__ float sm[];
    float* Qs = sm;                // [128][65]  Qs[d*65 + r]
    float* Ks = Qs + 128 * 65;     // [128][65]  Ks[d*65 + c]
    float* Vs = Ks + 128 * 65;     // [64][128]  Vs[k*128 + c]
    float* Pt = Vs + 64 * 128;     // [64][65]   Pt[c*65 + r]

    const int tid = threadIdx.x;
    const int ty = tid >> 4;
    const int tx = tid & 15;
    const int qtile = blockIdx.x;
    const int h = blockIdx.y;
    const int b = blockIdx.z;
    const int g = h >> 2;        // N_REP = 4

    const float* qbase = Q + ((size_t)b * SS + qtile * 64) * DIMM + h * HDD;
    const float* kbase = K + (size_t)b * SS * (NKVV * HDD) + g * HDD;
    const float* vbase = V + (size_t)b * SS * (NKVV * HDD) + g * HDD;

    for (int idx = tid; idx < 64 * 128; idx += 256) {
        int r = idx >> 7, d = idx & 127;
        Qs[d * 65 + r] = qbase[(size_t)r * DIMM + d];
    }

    const float scale = 0.08838834764831845f;
    float m[4], l[4], acc[4][8];
#pragma unroll
    for (int i = 0; i < 4; i++) {
        m[i] = -1e30f;
        l[i] = 0.0f;
#pragma unroll
        for (int j = 0; j < 8; j++) acc[i][j] = 0.0f;
    }

    for (int kt = 0; kt < SS / 64; kt++) {
        __syncthreads();
        for (int idx = tid; idx < 64 * 128; idx += 256) {
            int r = idx >> 7, d = idx & 127;
            Ks[d * 65 + r] = kbase[(size_t)(kt * 64 + r) * (NKVV * HDD) + d];
            Vs[r * 128 + d] = vbase[(size_t)(kt * 64 + r) * (NKVV * HDD) + d];
        }
        __syncthreads();

        float s[4][4];
#pragma unroll
        for (int i = 0; i < 4; i++)
#pragma unroll
            for (int j = 0; j < 4; j++) s[i][j] = 0.0f;

        for (int kk = 0; kk < 128; kk++) {
            float ra[4], rb[4];
#pragma unroll
            for (int i = 0; i < 4; i++) ra[i] = Qs[kk * 65 + ty * 4 + i];
#pragma unroll
            for (int j = 0; j < 4; j++) rb[j] = Ks[kk * 65 + tx * 4 + j];
#pragma unroll
            for (int i = 0; i < 4; i++)
#pragma unroll
                for (int j = 0; j < 4; j++)
                    s[i][j] = fmaf(ra[i], rb[j], s[i][j]);
        }

#pragma unroll
        for (int i = 0; i < 4; i++) {
            float mx = s[i][0];
#pragma unroll
            for (int j = 1; j < 4; j++) mx = fmaxf(mx, s[i][j]);
            mx *= scale;
#pragma unroll
            for (int off = 8; off > 0; off >>= 1)
                mx = fmaxf(mx, __shfl_xor_sync(0xffffffffu, mx, off));
            float mnew = fmaxf(m[i], mx);
            float corr = __expf(m[i] - mnew);
            float ls = 0.0f;
#pragma unroll
            for (int j = 0; j < 4; j++) {
                float p = __expf(s[i][j] * scale - mnew);
                Pt[(tx * 4 + j) * 65 + ty * 4 + i] = p;
                ls += p;
            }
#pragma unroll
            for (int off = 8; off > 0; off >>= 1)
                ls += __shfl_xor_sync(0xffffffffu, ls, off);
            l[i] = l[i] * corr + ls;
            m[i] = mnew;
#pragma unroll
            for (int jj = 0; jj < 8; jj++) acc[i][jj] *= corr;
        }
        __syncthreads();

        for (int k = 0; k < 64; k++) {
            float pa[4];
#pragma unroll
            for (int i = 0; i < 4; i++) pa[i] = Pt[k * 65 + ty * 4 + i];
            float vb[8];
#pragma unroll
            for (int jj = 0; jj < 8; jj++) vb[jj] = Vs[k * 128 + tx + 16 * jj];
#pragma unroll
            for (int i = 0; i < 4; i++)
#pragma unroll
                for (int jj = 0; jj < 8; jj++)
                    acc[i][jj] = fmaf(pa[i], vb[jj], acc[i][jj]);
        }
    }

    float* obase = O + ((size_t)b * SS + qtile * 64) * DIMM + h * HDD;
#pragma unroll
    for (int i = 0; i < 4; i++) {
        float inv = 1.0f / l[i];
#pragma unroll
        for (int jj = 0; jj < 8; jj++)
            obase[(size_t)(ty * 4 + i) * DIMM + tx + 16 * jj] = acc[i][jj] * inv;
    }
}

// ----------------------------------------------------------------------------
// Launch
// ----------------------------------------------------------------------------
extern "C" void kernel_launch(void* const* d_in, const int* in_sizes, int n_in,
                              void* d_out, int out_size)
{
    const float* x  = (const float*)d_in[0];
    const float* fc = (const float*)d_in[1];
    const float* wq = (const float*)d_in[2];
    const float* wk = (const float*)d_in[3];
    const float* wv = (const float*)d_in[4];
    const float* wo = (const float*)d_in[5];

    float* out  = (float*)d_out;                 // (b,s,DIM)
    float* kout = out + (size_t)OUT_ELEMS;       // new_k (b,s,NKV,HD)
    float* vout = kout + (size_t)KV_ELEMS;       // new_v (b,s,NKV,HD)

    float* qptr = nullptr;
    float* ctxptr = nullptr;
    cudaGetSymbolAddress((void**)&qptr, g_q);
    cudaGetSymbolAddress((void**)&ctxptr, g_ctx);

    size_t gemm_smem = GEMM_SMEM_FLOATS * sizeof(float); // 71680 B
    cudaFuncSetAttribute(gemm_tf32_kernel,
                         cudaFuncAttributeMaxDynamicSharedMemorySize,
                         (int)gemm_smem);

    // Q/K/V projections (tensor cores, tf32). K/V write straight to output buf.
    {
        dim3 gq(DIMM / 128, MROWS / 128);
        gemm_tf32_kernel<<<gq, 256, gemm_smem>>>(x, wq, qptr, MROWS, DIMM, DIMM);
        dim3 gkv((NKVV * HDD) / 128, MROWS / 128);
        gemm_tf32_kernel<<<gkv, 256, gemm_smem>>>(x, wk, kout, MROWS, NKVV * HDD, DIMM);
        gemm_tf32_kernel<<<gkv, 256, gemm_smem>>>(x, wv, vout, MROWS, NKVV * HDD, DIMM);
    }

    // RoPE (in place)
    {
        int totq = MROWS * NHH * 64;
        rope_kernel<<<(totq + 255) / 256, 256>>>(qptr, fc, MROWS, NHH);
        int totk = MROWS * NKVV * 64;
        rope_kernel<<<(totk + 255) / 256, 256>>>(kout, fc, MROWS, NKVV);
    }

    // Attention
    {
        size_t smem = ATTN_SMEM_FLOATS * sizeof(float);
        cudaFuncSetAttribute(attn_kernel,
                             cudaFuncAttributeMaxDynamicSharedMemorySize,
                             (int)smem);
        dim3 grid(SS / 64, NHH, BB);
        attn_kernel<<<grid, 256, smem>>>(qptr, kout, vout, ctxptr);
    }

    // Output projection (tensor cores, tf32)
    {
        dim3 go(DIMM / 128, MROWS / 128);
        gemm_tf32_kernel<<<go, 256, gemm_smem>>>(ctxptr, wo, out, MROWS, DIMM, DIMM);
    }
}